// round 14
// baseline (speedup 1.0000x reference)
#include <cuda_runtime.h>
#include <cstdint>

// Problem constants
#define BATCH 4
#define SEQ   2048
#define DMODEL 2048
#define NHEADS 16
#define HDIM  128
#define M_TOK (BATCH * SEQ)          // 8192
#define SL2 (0.08838834764831845f * 1.4426950408889634f)

// ---------------------------------------------------------------------------
// Scratch
// ---------------------------------------------------------------------------
__device__ float g_q[M_TOK * DMODEL];
__device__ float g_k[M_TOK * DMODEL];
__device__ float g_v[M_TOK * DMODEL];
__device__ float g_attn[M_TOK * DMODEL];
// tf32-prerounded copies of inputs
__device__ float g_x[M_TOK * DMODEL];
__device__ float g_wq[DMODEL * DMODEL];
__device__ float g_wk[DMODEL * DMODEL];
__device__ float g_wv[DMODEL * DMODEL];
__device__ float g_wo[DMODEL * DMODEL];

// ---------------------------------------------------------------------------
// Common PTX helpers
// ---------------------------------------------------------------------------
__device__ __forceinline__ uint32_t f2tf32(float f) {
    uint32_t r;
    asm("cvt.rna.tf32.f32 %0, %1;" : "=r"(r) : "f"(f));
    return r;
}
__device__ __forceinline__ void mma_tf32(float c[4], const uint32_t a[4], const uint32_t b[2]) {
    asm volatile(
        "mma.sync.aligned.m16n8k8.row.col.f32.tf32.tf32.f32 "
        "{%0,%1,%2,%3}, {%4,%5,%6,%7}, {%8,%9}, {%0,%1,%2,%3};"
        : "+f"(c[0]), "+f"(c[1]), "+f"(c[2]), "+f"(c[3])
        : "r"(a[0]), "r"(a[1]), "r"(a[2]), "r"(a[3]), "r"(b[0]), "r"(b[1]));
}
__device__ __forceinline__ float ex2(float x) {
    float y;
    asm("ex2.approx.f32 %0, %1;" : "=f"(y) : "f"(x));
    return y;
}
__device__ __forceinline__ void cp16(float* dst_smem, const float* src_gmem) {
    uint32_t d = (uint32_t)__cvta_generic_to_shared(dst_smem);
    asm volatile("cp.async.cg.shared.global [%0], [%1], 16;" :: "r"(d), "l"(src_gmem));
}
__device__ __forceinline__ void cp_commit() {
    asm volatile("cp.async.commit_group;");
}
template<int N> __device__ __forceinline__ void cp_wait() {
    asm volatile("cp.async.wait_group %0;" :: "n"(N));
}

// ---------------------------------------------------------------------------
// Pre-round fp32 -> tf32 bit pattern
// ---------------------------------------------------------------------------
__global__ __launch_bounds__(256)
void preround_kernel(const float4* __restrict__ src, float4* __restrict__ dst, int n4)
{
    int i = blockIdx.x * 256 + threadIdx.x;
    if (i < n4) {
        float4 v = src[i];
        v.x = __uint_as_float(f2tf32(v.x));
        v.y = __uint_as_float(f2tf32(v.y));
        v.z = __uint_as_float(f2tf32(v.z));
        v.w = __uint_as_float(f2tf32(v.w));
        dst[i] = v;
    }
}

// ---------------------------------------------------------------------------
// TF32 mma.sync GEMM, CTA tile 128x128, Ktile 32, 3-stage cp.async pipeline,
// 2 CTAs/SM. 8 warps (2x4), warp tile 64x32. Inputs pre-tf32-rounded.
//   sA [m][k] stride 36  : A-frag banks (4g+t) all distinct
//   sB [k][n] stride 136 : B-frag banks (8t+g) all distinct
// mode 0: plain fp32 store; mode 1: split-head store, tf32-rounded.
// ---------------------------------------------------------------------------
#define GK DMODEL
#define GN DMODEL
#define KT 32
#define SA_ST 36
#define SB_ST 136
#define TA_F (128 * SA_ST)     // 4608 floats
#define TB_F (KT * SB_ST)      // 4352 floats
#define NBUF 3
#define GEMM_SM_BYTES (NBUF * (TA_F + TB_F) * 4)   // 107520 B

__global__ __launch_bounds__(256, 2)
void gemm_tf32_kernel(const float* __restrict__ A,
                      const float* __restrict__ W,
                      const float* __restrict__ bias,
                      float* __restrict__ dst,
                      int mode)
{
    extern __shared__ float gsm[];
    float* sAb = gsm;                    // [NBUF][TA_F]
    float* sBb = gsm + NBUF * TA_F;      // [NBUF][TB_F]

    const int tid  = threadIdx.x;
    const int wid  = tid >> 5;
    const int lane = tid & 31;
    const int g    = lane >> 2;
    const int t    = lane & 3;

    const int bm = blockIdx.y * 128;
    const int bn = blockIdx.x * 128;

    const int warp_m = (wid >> 2) * 64;   // 0 or 64
    const int warp_n = (wid & 3) * 32;    // 0,32,64,96

    // loader assignment (Ktile = 32)
    const int a_row = tid >> 1;            // 0..127
    const int a_kc  = (tid & 1) * 16;      // 0 or 16; 4 cp16 each
    const int b_row = tid >> 3;            // 0..31
    const int b_col = (tid & 7) * 16;      // 0..112; 4 cp16 each

    const float* Aptr = A + (size_t)(bm + a_row) * GK + a_kc;
    const float* Wptr = W + (size_t)b_row * GN + bn + b_col;

    float acc[4][4][4];
#pragma unroll
    for (int i = 0; i < 4; i++)
#pragma unroll
        for (int j = 0; j < 4; j++)
#pragma unroll
            for (int r = 0; r < 4; r++) acc[i][j][r] = 0.f;

#define ISSUE(TI)                                                              \
    do {                                                                       \
        const int _buf = (TI) % NBUF;                                          \
        float* pa = sAb + _buf * TA_F + a_row * SA_ST + a_kc;                  \
        float* pb = sBb + _buf * TB_F + b_row * SB_ST + b_col;                 \
        const float* _as = Aptr + (TI) * KT;                                   \
        const float* _bs = Wptr + (size_t)((TI) * KT) * GN;                    \
        cp16(pa,      _as);                                                    \
        cp16(pa + 4,  _as + 4);                                                \
        cp16(pa + 8,  _as + 8);                                                \
        cp16(pa + 12, _as + 12);                                               \
        cp16(pb,      _bs);                                                    \
        cp16(pb + 4,  _bs + 4);                                                \
        cp16(pb + 8,  _bs + 8);                                                \
        cp16(pb + 12, _bs + 12);                                               \
        cp_commit();                                                           \
    } while (0)

    ISSUE(0);
    ISSUE(1);

    const int NT = GK / KT;   // 64
    for (int i = 0; i < NT; i++) {
        if (i + 1 < NT) cp_wait<1>(); else cp_wait<0>();
        __syncthreads();                 // tile i visible; all threads done with buf (i+2)%3
        if (i + 2 < NT) ISSUE(i + 2);

        const float* cA = sAb + (i % NBUF) * TA_F;
        const float* cB = sBb + (i % NBUF) * TB_F;
#pragma unroll
        for (int kk = 0; kk < KT; kk += 8) {
            uint32_t afr[4][4];
            uint32_t bfr[4][2];
#pragma unroll
            for (int mf = 0; mf < 4; mf++) {
                const int m = warp_m + 16 * mf + g;
                afr[mf][0] = __float_as_uint(cA[(m)     * SA_ST + kk + t]);
                afr[mf][1] = __float_as_uint(cA[(m + 8) * SA_ST + kk + t]);
                afr[mf][2] = __float_as_uint(cA[(m)     * SA_ST + kk + t + 4]);
                afr[mf][3] = __float_as_uint(cA[(m + 8) * SA_ST + kk + t + 4]);
            }
#pragma unroll
            for (int nf = 0; nf < 4; nf++) {
                const int n = warp_n + 8 * nf + g;
                bfr[nf][0] = __float_as_uint(cB[(kk + t)     * SB_ST + n]);
                bfr[nf][1] = __float_as_uint(cB[(kk + t + 4) * SB_ST + n]);
            }
#pragma unroll
            for (int mf = 0; mf < 4; mf++)
#pragma unroll
                for (int nf = 0; nf < 4; nf++)
                    mma_tf32(acc[mf][nf], afr[mf], bfr[nf]);
        }
    }
#undef ISSUE

    // ---- epilogue: bias add + store ----
#pragma unroll
    for (int mf = 0; mf < 4; mf++) {
#pragma unroll
        for (int nf = 0; nf < 4; nf++) {
            const int col = bn + warp_n + 8 * nf + 2 * t;
            const float b0 = bias[col];
            const float b1 = bias[col + 1];
#pragma unroll
            for (int half = 0; half < 2; half++) {
                const int row = bm + warp_m + 16 * mf + g + 8 * half;
                float2 v;
                v.x = acc[mf][nf][2 * half + 0] + b0;
                v.y = acc[mf][nf][2 * half + 1] + b1;
                if (mode == 0) {
                    *(float2*)&dst[(size_t)row * GN + col] = v;
                } else {
                    v.x = __uint_as_float(f2tf32(v.x));
                    v.y = __uint_as_float(f2tf32(v.y));
                    const int b_ = row >> 11;
                    const int s_ = row & 2047;
                    const int h_ = col >> 7;
                    const int d_ = col & 127;
                    *(float2*)&dst[(((size_t)(b_ * NHEADS + h_)) * SEQ + s_) * HDIM + d_] = v;
                }
            }
        }
    }
}

// ---------------------------------------------------------------------------
// Tensor-core flash attention (tf32 mma.sync), causal — unchanged (round 8).
// ---------------------------------------------------------------------------
#define K_ST 132
#define V_ST 136
#define Q_ST 136
#define P_ST 136
#define SM_QT_F   (128 * Q_ST)
#define SM_K_F    (2 * 64 * K_ST)
#define SM_V_F    (64 * V_ST)
#define SM_PT_F   (64 * P_ST)
#define SM_RED_F  128
#define SMA_FLOATS (SM_QT_F + SM_K_F + SM_V_F + SM_PT_F + SM_RED_F)
#define SMA_BYTES  (SMA_FLOATS * 4)

__device__ __forceinline__ void load_k_tile(float* dst, const float* src, int tid) {
#pragma unroll
    for (int j = 0; j < 8; j++) {
        int c = tid + j * 256;
        int row = c >> 5;
        int c16 = (c & 31) * 4;
        cp16(dst + row * K_ST + c16, src + (size_t)row * HDIM + c16);
    }
}
__device__ __forceinline__ void load_v_tile(float* dst, const float* src, int tid) {
#pragma unroll
    for (int j = 0; j < 8; j++) {
        int c = tid + j * 256;
        int row = c >> 5;
        int c16 = (c & 31) * 4;
        cp16(dst + row * V_ST + c16, src + (size_t)row * HDIM + c16);
    }
}

__global__ __launch_bounds__(256, 1)
void attn_mma_kernel(const float* __restrict__ Q,
                     const float* __restrict__ K,
                     const float* __restrict__ V,
                     float* __restrict__ O)
{
    extern __shared__ float sm[];
    float* sQt  = sm;
    float* sK   = sQt + SM_QT_F;
    float* sV   = sK + SM_K_F;
    float* sPT  = sV + SM_V_F;
    float* sRed = sPT + SM_PT_F;

    const int tid  = threadIdx.x;
    const int wid  = tid >> 5;
    const int lane = tid & 31;
    const int g    = lane >> 2;
    const int t    = lane & 3;
    const int qw   = 16 * wid;

    const int qb = (gridDim.x - 1) - blockIdx.x;
    const int h  = blockIdx.y;
    const int b  = blockIdx.z;

    const size_t head = ((size_t)(b * NHEADS + h)) * SEQ * HDIM;
    const float* Qb = Q + head + (size_t)qb * 128 * HDIM;
    const float* Kb = K + head;
    const float* Vb = V + head;

    for (int i = tid; i < 128 * 32; i += 256) {
        int c4 = i >> 7;
        int q  = i & 127;
        float4 v = *(const float4*)(Qb + (size_t)q * HDIM + c4 * 4);
        sQt[(4 * c4 + 0) * Q_ST + q] = v.x;
        sQt[(4 * c4 + 1) * Q_ST + q] = v.y;
        sQt[(4 * c4 + 2) * Q_ST + q] = v.z;
        sQt[(4 * c4 + 3) * Q_ST + q] = v.w;
    }

    const int ntiles = 2 * (qb + 1);

    load_k_tile(sK, Kb, tid);            cp_commit();
    load_v_tile(sV, Vb, tid);            cp_commit();

    float m_i[2][2], l_i[2][2];
    float acc_o[16][4];
#pragma unroll
    for (int nf = 0; nf < 2; nf++)
#pragma unroll
        for (int par = 0; par < 2; par++) { m_i[nf][par] = -1e30f; l_i[nf][par] = 0.f; }
#pragma unroll
    for (int i = 0; i < 16; i++)
#pragma unroll
        for (int r = 0; r < 4; r++) acc_o[i][r] = 0.f;

    __syncthreads();

    for (int kb = 0; kb < ntiles; kb++) {
        const bool has_next = (kb + 1) < ntiles;
        if (has_next) {
            load_k_tile(sK + ((kb + 1) & 1) * 64 * K_ST,
                        Kb + (size_t)(kb + 1) * 64 * HDIM, tid);
            cp_commit();
        }
        if (has_next) cp_wait<2>(); else cp_wait<1>();
        __syncthreads();

        const float* cK = sK + (kb & 1) * 64 * K_ST;
        const bool active = (kb * 64) <= (qb * 128 + qw + 15);

        float p[4][2][4];
        if (active) {
#pragma unroll
            for (int mf = 0; mf < 4; mf++)
#pragma unroll
                for (int nf = 0; nf < 2; nf++)
#pragma unroll
                    for (int r = 0; r < 4; r++) p[mf][nf][r] = 0.f;

#pragma unroll 4
            for (int kk = 0; kk < HDIM; kk += 8) {
                uint32_t afr[4][4];
#pragma unroll
                for (int mf = 0; mf < 4; mf++) {
                    const int m = 16 * mf + g;
                    afr[mf][0] = __float_as_uint(cK[(m)     * K_ST + kk + t]);
                    afr[mf][1] = __float_as_uint(cK[(m + 8) * K_ST + kk + t]);
                    afr[mf][2] = __float_as_uint(cK[(m)     * K_ST + kk + t + 4]);
                    afr[mf][3] = __float_as_uint(cK[(m + 8) * K_ST + kk + t + 4]);
                }
                uint32_t bfr[2][2];
#pragma unroll
                for (int nf = 0; nf < 2; nf++) {
                    const int qn = qw + 8 * nf + g;
                    bfr[nf][0] = __float_as_uint(sQt[(kk + t)     * Q_ST + qn]);
                    bfr[nf][1] = __float_as_uint(sQt[(kk + t + 4) * Q_ST + qn]);
                }
#pragma unroll
                for (int mf = 0; mf < 4; mf++)
#pragma unroll
                    for (int nf = 0; nf < 2; nf++)
                        mma_tf32(p[mf][nf], afr[mf], bfr[nf]);
            }

            const bool diag = (kb >= ntiles - 2);
            float mx[2][2] = {{-1e30f, -1e30f}, {-1e30f, -1e30f}};
#pragma unroll
            for (int mf = 0; mf < 4; mf++)
#pragma unroll
                for (int nf = 0; nf < 2; nf++) {
                    const int kg = kb * 64 + 16 * mf + g;
                    const int qc = qb * 128 + qw + 8 * nf + 2 * t;
#pragma unroll
                    for (int e = 0; e < 4; e++) {
                        const int kge = kg + ((e >= 2) ? 8 : 0);
                        const int qce = qc + (e & 1);
                        float v = p[mf][nf][e] * SL2;
                        if (diag && kge > qce) v = -1e30f;
                        p[mf][nf][e] = v;
                    }
                    mx[nf][0] = fmaxf(mx[nf][0], fmaxf(p[mf][nf][0], p[mf][nf][2]));
                    mx[nf][1] = fmaxf(mx[nf][1], fmaxf(p[mf][nf][1], p[mf][nf][3]));
                }
#pragma unroll
            for (int nf = 0; nf < 2; nf++)
#pragma unroll
                for (int par = 0; par < 2; par++) {
                    float v = mx[nf][par];
                    v = fmaxf(v, __shfl_xor_sync(0xffffffffu, v, 4));
                    v = fmaxf(v, __shfl_xor_sync(0xffffffffu, v, 8));
                    v = fmaxf(v, __shfl_xor_sync(0xffffffffu, v, 16));
                    mx[nf][par] = v;
                }
            float alpha[2][2];
#pragma unroll
            for (int nf = 0; nf < 2; nf++)
#pragma unroll
                for (int par = 0; par < 2; par++) {
                    const float m_new = fmaxf(m_i[nf][par], mx[nf][par]);
                    alpha[nf][par] = ex2(m_i[nf][par] - m_new);
                    m_i[nf][par] = m_new;
                }
            float sum[2][2] = {{0.f, 0.f}, {0.f, 0.f}};
#pragma unroll
            for (int mf = 0; mf < 4; mf++)
#pragma unroll
                for (int nf = 0; nf < 2; nf++) {
                    p[mf][nf][0] = ex2(p[mf][nf][0] - m_i[nf][0]);
                    p[mf][nf][1] = ex2(p[mf][nf][1] - m_i[nf][1]);
                    p[mf][nf][2] = ex2(p[mf][nf][2] - m_i[nf][0]);
                    p[mf][nf][3] = ex2(p[mf][nf][3] - m_i[nf][1]);
                    sum[nf][0] += p[mf][nf][0] + p[mf][nf][2];
                    sum[nf][1] += p[mf][nf][1] + p[mf][nf][3];
                }
#pragma unroll
            for (int nf = 0; nf < 2; nf++)
#pragma unroll
                for (int par = 0; par < 2; par++) {
                    float v = sum[nf][par];
                    v += __shfl_xor_sync(0xffffffffu, v, 4);
                    v += __shfl_xor_sync(0xffffffffu, v, 8);
                    v += __shfl_xor_sync(0xffffffffu, v, 16);
                    l_i[nf][par] = l_i[nf][par] * alpha[nf][par] + v;
                }

#pragma unroll
            for (int mf = 0; mf < 4; mf++)
#pragma unroll
                for (int nf = 0; nf < 2; nf++) {
                    const int kr = 16 * mf + g;
                    const int qc = qw + 8 * nf + 2 * t;
                    sPT[(kr)     * P_ST + qc]     = __uint_as_float(f2tf32(p[mf][nf][0]));
                    sPT[(kr)     * P_ST + qc + 1] = __uint_as_float(f2tf32(p[mf][nf][1]));
                    sPT[(kr + 8) * P_ST + qc]     = __uint_as_float(f2tf32(p[mf][nf][2]));
                    sPT[(kr + 8) * P_ST + qc + 1] = __uint_as_float(f2tf32(p[mf][nf][3]));
                }
            if (lane < 4) {
#pragma unroll
                for (int nf = 0; nf < 2; nf++)
#pragma unroll
                    for (int par = 0; par < 2; par++)
                        sRed[qw + 8 * nf + 2 * lane + par] = alpha[nf][par];
            }
            __syncwarp();
            const float al0 = sRed[qw + g];
            const float al1 = sRed[qw + g + 8];
#pragma unroll
            for (int nf2 = 0; nf2 < 16; nf2++) {
                acc_o[nf2][0] *= al0; acc_o[nf2][1] *= al0;
                acc_o[nf2][2] *= al1; acc_o[nf2][3] *= al1;
            }
        }

        if (has_next) cp_wait<1>(); else cp_wait<0>();
        __syncthreads();

        if (active) {
#pragma unroll 2
            for (int kk = 0; kk < 64; kk += 8) {
                uint32_t va[4];
                va[0] = __float_as_uint(sPT[(kk + t)     * P_ST + qw + g]);
                va[1] = __float_as_uint(sPT[(kk + t)     * P_ST + qw + g + 8]);
                va[2] = __float_as_uint(sPT[(kk + t + 4) * P_ST + qw + g]);
                va[3] = __float_as_uint(sPT[(kk + t + 4) * P_ST + qw + g + 8]);
#pragma unroll
                for (int nf2 = 0; nf2 < 16; nf2++) {
                    uint32_t vb[2];
                    vb[0] = __float_as_uint(sV[(kk + t)     * V_ST + 8 * nf2 + g]);
                    vb[1] = __float_as_uint(sV[(kk + t + 4) * V_ST + 8 * nf2 + g]);
                    mma_tf32(acc_o[nf2], va, vb);
                }
            }
        }

        __syncthreads();
        if (has_next) {
            load_v_tile(sV, Vb + (size_t)(kb + 1) * 64 * HDIM, tid);
            cp_commit();
        }
    }

    if (lane < 4) {
#pragma unroll
        for (int nf = 0; nf < 2; nf++)
#pragma unroll
            for (int par = 0; par < 2; par++)
                sRed[qw + 8 * nf + 2 * lane + par] = l_i[nf][par];
    }
    __syncwarp();
    const float il0 = 1.f / sRed[qw + g];
    const float il1 = 1.f / sRed[qw + g + 8];

    const int q0 = qb * 128 + qw + g;
    const int q1 = q0 + 8;
    const size_t base0 = ((size_t)b * SEQ + q0) * DMODEL + h * HDIM;
    const size_t base1 = ((size_t)b * SEQ + q1) * DMODEL + h * HDIM;
#pragma unroll
    for (int nf2 = 0; nf2 < 16; nf2++) {
        const int d = 8 * nf2 + 2 * t;
        float2 v0, v1;
        v0.x = __uint_as_float(f2tf32(acc_o[nf2][0] * il0));
        v0.y = __uint_as_float(f2tf32(acc_o[nf2][1] * il0));
        v1.x = __uint_as_float(f2tf32(acc_o[nf2][2] * il1));
        v1.y = __uint_as_float(f2tf32(acc_o[nf2][3] * il1));
        *(float2*)&O[base0 + d] = v0;
        *(float2*)&O[base1 + d] = v1;
    }
}

// ---------------------------------------------------------------------------
// Launch
// ---------------------------------------------------------------------------
extern "C" void kernel_launch(void* const* d_in, const int* in_sizes, int n_in,
                              void* d_out, int out_size)
{
    const float* x  = (const float*)d_in[0];
    const float* Wq = (const float*)d_in[1];
    const float* bq = (const float*)d_in[2];
    const float* Wk = (const float*)d_in[3];
    const float* bk = (const float*)d_in[4];
    const float* Wv = (const float*)d_in[5];
    const float* bv = (const float*)d_in[6];
    const float* Wo = (const float*)d_in[7];
    const float* bo = (const float*)d_in[8];
    float* out = (float*)d_out;

    float *q, *k, *v, *attn, *xr, *wq, *wk, *wv, *wo;
    cudaGetSymbolAddress((void**)&q,    g_q);
    cudaGetSymbolAddress((void**)&k,    g_k);
    cudaGetSymbolAddress((void**)&v,    g_v);
    cudaGetSymbolAddress((void**)&attn, g_attn);
    cudaGetSymbolAddress((void**)&xr,   g_x);
    cudaGetSymbolAddress((void**)&wq,   g_wq);
    cudaGetSymbolAddress((void**)&wk,   g_wk);
    cudaGetSymbolAddress((void**)&wv,   g_wv);
    cudaGetSymbolAddress((void**)&wo,   g_wo);

    cudaFuncSetAttribute(attn_mma_kernel,
                         cudaFuncAttributeMaxDynamicSharedMemorySize, SMA_BYTES);
    cudaFuncSetAttribute(gemm_tf32_kernel,
                         cudaFuncAttributeMaxDynamicSharedMemorySize, GEMM_SM_BYTES);

    // pre-round inputs to tf32 bit patterns
    const int n4x = M_TOK * DMODEL / 4;
    const int n4w = DMODEL * DMODEL / 4;
    preround_kernel<<<n4x / 256, 256>>>((const float4*)x,  (float4*)xr, n4x);
    preround_kernel<<<n4w / 256, 256>>>((const float4*)Wq, (float4*)wq, n4w);
    preround_kernel<<<n4w / 256, 256>>>((const float4*)Wk, (float4*)wk, n4w);
    preround_kernel<<<n4w / 256, 256>>>((const float4*)Wv, (float4*)wv, n4w);
    preround_kernel<<<n4w / 256, 256>>>((const float4*)Wo, (float4*)wo, n4w);

    dim3 gemm_grid(GN / 128, M_TOK / 128);   // (16, 64)

    gemm_tf32_kernel<<<gemm_grid, 256, GEMM_SM_BYTES>>>(xr, wq, bq, q, 1);
    gemm_tf32_kernel<<<gemm_grid, 256, GEMM_SM_BYTES>>>(xr, wk, bk, k, 1);
    gemm_tf32_kernel<<<gemm_grid, 256, GEMM_SM_BYTES>>>(xr, wv, bv, v, 1);

    attn_mma_kernel<<<dim3(SEQ / 128, NHEADS, BATCH), 256, SMA_BYTES>>>(q, k, v, attn);

    gemm_tf32_kernel<<<gemm_grid, 256, GEMM_SM_BYTES>>>(attn, wo, bo, out, 0);
}

// round 15
// speedup vs baseline: 1.2049x; 1.2049x over previous
#include <cuda_runtime.h>
#include <cstdint>

// Problem constants
#define BATCH 4
#define SEQ   2048
#define DMODEL 2048
#define NHEADS 16
#define HDIM  128
#define M_TOK (BATCH * SEQ)          // 8192
#define SL2 (0.08838834764831845f * 1.4426950408889634f)

// ---------------------------------------------------------------------------
// Scratch
// ---------------------------------------------------------------------------
__device__ float g_q[M_TOK * DMODEL];
__device__ float g_k[M_TOK * DMODEL];
__device__ float g_v[M_TOK * DMODEL];
__device__ float g_attn[M_TOK * DMODEL];
// tf32-prerounded copies of inputs
__device__ float g_x[M_TOK * DMODEL];
__device__ float g_wq[DMODEL * DMODEL];
__device__ float g_wk[DMODEL * DMODEL];
__device__ float g_wv[DMODEL * DMODEL];
__device__ float g_wo[DMODEL * DMODEL];

// ---------------------------------------------------------------------------
// Common PTX helpers
// ---------------------------------------------------------------------------
__device__ __forceinline__ uint32_t f2tf32(float f) {
    uint32_t r;
    asm("cvt.rna.tf32.f32 %0, %1;" : "=r"(r) : "f"(f));
    return r;
}
__device__ __forceinline__ void mma_tf32(float c[4], const uint32_t a[4], const uint32_t b[2]) {
    asm volatile(
        "mma.sync.aligned.m16n8k8.row.col.f32.tf32.tf32.f32 "
        "{%0,%1,%2,%3}, {%4,%5,%6,%7}, {%8,%9}, {%0,%1,%2,%3};"
        : "+f"(c[0]), "+f"(c[1]), "+f"(c[2]), "+f"(c[3])
        : "r"(a[0]), "r"(a[1]), "r"(a[2]), "r"(a[3]), "r"(b[0]), "r"(b[1]));
}
__device__ __forceinline__ float ex2(float x) {
    float y;
    asm("ex2.approx.f32 %0, %1;" : "=f"(y) : "f"(x));
    return y;
}
__device__ __forceinline__ void cp16(float* dst_smem, const float* src_gmem) {
    uint32_t d = (uint32_t)__cvta_generic_to_shared(dst_smem);
    asm volatile("cp.async.cg.shared.global [%0], [%1], 16;" :: "r"(d), "l"(src_gmem));
}
__device__ __forceinline__ void cp_commit() {
    asm volatile("cp.async.commit_group;");
}
template<int N> __device__ __forceinline__ void cp_wait() {
    asm volatile("cp.async.wait_group %0;" :: "n"(N));
}

// ---------------------------------------------------------------------------
// Fused pre-round: x (2^22 float4) then Wq,Wk,Wv,Wo (2^20 float4 each)
// ---------------------------------------------------------------------------
#define X_F4 (1 << 22)
#define W_F4 (1 << 20)
#define PR_TOTAL_F4 (X_F4 + 4 * W_F4)   // 2^22 + 2^22 = 2^23

__global__ __launch_bounds__(256)
void preround5_kernel(const float4* __restrict__ x,  float4* __restrict__ xr,
                      const float4* __restrict__ w0, float4* __restrict__ r0,
                      const float4* __restrict__ w1, float4* __restrict__ r1,
                      const float4* __restrict__ w2, float4* __restrict__ r2,
                      const float4* __restrict__ w3, float4* __restrict__ r3)
{
    int i = blockIdx.x * 256 + threadIdx.x;
    const float4* s;
    float4* d;
    int off;
    if (i < X_F4) {
        s = x; d = xr; off = i;
    } else {
        int j = i - X_F4;
        int r = j >> 20;
        off = j & (W_F4 - 1);
        if (r == 0)      { s = w0; d = r0; }
        else if (r == 1) { s = w1; d = r1; }
        else if (r == 2) { s = w2; d = r2; }
        else             { s = w3; d = r3; }
    }
    float4 v = s[off];
    v.x = __uint_as_float(f2tf32(v.x));
    v.y = __uint_as_float(f2tf32(v.y));
    v.z = __uint_as_float(f2tf32(v.z));
    v.w = __uint_as_float(f2tf32(v.w));
    d[off] = v;
}

// ---------------------------------------------------------------------------
// TF32 mma.sync GEMM body — EXACT Round-8 structure (known-good local optimum).
// CTA tile 128x128, Ktile 16, 3-stage cp.async, 2 CTAs/SM, 8 warps (2x4),
// warp tile 64x32.  sA [m][k] st20, sB [k][n] st136 (both conflict-free).
// mode 0: plain fp32 store; mode 1: split-head store, tf32-rounded.
// ---------------------------------------------------------------------------
#define GK DMODEL
#define GN DMODEL
#define SA_ST 20
#define SB_ST 136
#define TA_F (128 * SA_ST)     // 2560 floats
#define TB_F (16 * SB_ST)      // 2176 floats
#define GEMM_SM_BYTES (3 * (TA_F + TB_F) * 4)   // 56832 B

__device__ __forceinline__ void gemm_body(const float* __restrict__ A,
                                          const float* __restrict__ W,
                                          const float* __restrict__ bias,
                                          float* __restrict__ dst,
                                          int mode)
{
    extern __shared__ float gsm[];
    float* sAb = gsm;                 // [3][TA_F]
    float* sBb = gsm + 3 * TA_F;      // [3][TB_F]

    const int tid  = threadIdx.x;
    const int wid  = tid >> 5;
    const int lane = tid & 31;
    const int g    = lane >> 2;
    const int t    = lane & 3;

    const int bm = blockIdx.y * 128;
    const int bn = blockIdx.x * 128;

    const int warp_m = (wid >> 2) * 64;   // 0 or 64
    const int warp_n = (wid & 3) * 32;    // 0,32,64,96

    const int a_row = tid >> 1;            // 0..127
    const int a_kc  = (tid & 1) * 4;       // 0 or 4 (+8 second piece)
    const int b_row = tid >> 4;            // 0..15
    const int b_col = (tid & 15) * 4;      // 0..60 (+64 second piece)

    const float* Aptr = A + (size_t)(bm + a_row) * GK + a_kc;
    const float* Wptr = W + (size_t)b_row * GN + bn + b_col;

    float acc[4][4][4];
#pragma unroll
    for (int i = 0; i < 4; i++)
#pragma unroll
        for (int j = 0; j < 4; j++)
#pragma unroll
            for (int r = 0; r < 4; r++) acc[i][j][r] = 0.f;

#define ISSUE(TI)                                                              \
    do {                                                                       \
        const int _buf = (TI) % 3;                                             \
        float* pa = sAb + _buf * TA_F;                                         \
        float* pb = sBb + _buf * TB_F;                                         \
        const int _k0 = (TI) * 16;                                             \
        cp16(pa + a_row * SA_ST + a_kc,     Aptr + _k0);                       \
        cp16(pa + a_row * SA_ST + a_kc + 8, Aptr + _k0 + 8);                   \
        cp16(pb + b_row * SB_ST + b_col,      Wptr + (size_t)_k0 * GN);        \
        cp16(pb + b_row * SB_ST + b_col + 64, Wptr + (size_t)_k0 * GN + 64);   \
        cp_commit();                                                           \
    } while (0)

    ISSUE(0);
    ISSUE(1);

    const int NT = GK / 16;   // 128
    for (int i = 0; i < NT; i++) {
        if (i + 1 < NT) cp_wait<1>(); else cp_wait<0>();
        __syncthreads();
        if (i + 2 < NT) ISSUE(i + 2);

        const float* cA = sAb + (i % 3) * TA_F;
        const float* cB = sBb + (i % 3) * TB_F;
#pragma unroll
        for (int kk = 0; kk < 16; kk += 8) {
            uint32_t afr[4][4];
            uint32_t bfr[4][2];
#pragma unroll
            for (int mf = 0; mf < 4; mf++) {
                const int m = warp_m + 16 * mf + g;
                afr[mf][0] = __float_as_uint(cA[(m)     * SA_ST + kk + t]);
                afr[mf][1] = __float_as_uint(cA[(m + 8) * SA_ST + kk + t]);
                afr[mf][2] = __float_as_uint(cA[(m)     * SA_ST + kk + t + 4]);
                afr[mf][3] = __float_as_uint(cA[(m + 8) * SA_ST + kk + t + 4]);
            }
#pragma unroll
            for (int nf = 0; nf < 4; nf++) {
                const int n = warp_n + 8 * nf + g;
                bfr[nf][0] = __float_as_uint(cB[(kk + t)     * SB_ST + n]);
                bfr[nf][1] = __float_as_uint(cB[(kk + t + 4) * SB_ST + n]);
            }
#pragma unroll
            for (int mf = 0; mf < 4; mf++)
#pragma unroll
                for (int nf = 0; nf < 4; nf++)
                    mma_tf32(acc[mf][nf], afr[mf], bfr[nf]);
        }
    }
#undef ISSUE

    // ---- epilogue: bias add + store ----
#pragma unroll
    for (int mf = 0; mf < 4; mf++) {
#pragma unroll
        for (int nf = 0; nf < 4; nf++) {
            const int col = bn + warp_n + 8 * nf + 2 * t;
            const float b0 = bias[col];
            const float b1 = bias[col + 1];
#pragma unroll
            for (int half = 0; half < 2; half++) {
                const int row = bm + warp_m + 16 * mf + g + 8 * half;
                float2 v;
                v.x = acc[mf][nf][2 * half + 0] + b0;
                v.y = acc[mf][nf][2 * half + 1] + b1;
                if (mode == 0) {
                    *(float2*)&dst[(size_t)row * GN + col] = v;
                } else {
                    v.x = __uint_as_float(f2tf32(v.x));
                    v.y = __uint_as_float(f2tf32(v.y));
                    const int b_ = row >> 11;
                    const int s_ = row & 2047;
                    const int h_ = col >> 7;
                    const int d_ = col & 127;
                    *(float2*)&dst[(((size_t)(b_ * NHEADS + h_)) * SEQ + s_) * HDIM + d_] = v;
                }
            }
        }
    }
}

// Fused QKV: one launch, blockIdx.z selects projection. One drain tail not three.
__global__ __launch_bounds__(256, 2)
void gemm_qkv_kernel(const float* __restrict__ A,
                     const float* __restrict__ W0, const float* __restrict__ W1,
                     const float* __restrict__ W2,
                     const float* __restrict__ b0, const float* __restrict__ b1,
                     const float* __restrict__ b2,
                     float* __restrict__ d0, float* __restrict__ d1,
                     float* __restrict__ d2)
{
    const float* W;
    const float* bias;
    float* dst;
    if (blockIdx.z == 0)      { W = W0; bias = b0; dst = d0; }
    else if (blockIdx.z == 1) { W = W1; bias = b1; dst = d1; }
    else                      { W = W2; bias = b2; dst = d2; }
    gemm_body(A, W, bias, dst, 1);
}

__global__ __launch_bounds__(256, 2)
void gemm_tf32_kernel(const float* __restrict__ A,
                      const float* __restrict__ W,
                      const float* __restrict__ bias,
                      float* __restrict__ dst,
                      int mode)
{
    gemm_body(A, W, bias, dst, mode);
}

// ---------------------------------------------------------------------------
// Tensor-core flash attention (tf32 mma.sync), causal — unchanged (round 8).
// ---------------------------------------------------------------------------
#define K_ST 132
#define V_ST 136
#define Q_ST 136
#define P_ST 136
#define SM_QT_F   (128 * Q_ST)
#define SM_K_F    (2 * 64 * K_ST)
#define SM_V_F    (64 * V_ST)
#define SM_PT_F   (64 * P_ST)
#define SM_RED_F  128
#define SMA_FLOATS (SM_QT_F + SM_K_F + SM_V_F + SM_PT_F + SM_RED_F)
#define SMA_BYTES  (SMA_FLOATS * 4)

__device__ __forceinline__ void load_k_tile(float* dst, const float* src, int tid) {
#pragma unroll
    for (int j = 0; j < 8; j++) {
        int c = tid + j * 256;
        int row = c >> 5;
        int c16 = (c & 31) * 4;
        cp16(dst + row * K_ST + c16, src + (size_t)row * HDIM + c16);
    }
}
__device__ __forceinline__ void load_v_tile(float* dst, const float* src, int tid) {
#pragma unroll
    for (int j = 0; j < 8; j++) {
        int c = tid + j * 256;
        int row = c >> 5;
        int c16 = (c & 31) * 4;
        cp16(dst + row * V_ST + c16, src + (size_t)row * HDIM + c16);
    }
}

__global__ __launch_bounds__(256, 1)
void attn_mma_kernel(const float* __restrict__ Q,
                     const float* __restrict__ K,
                     const float* __restrict__ V,
                     float* __restrict__ O)
{
    extern __shared__ float sm[];
    float* sQt  = sm;
    float* sK   = sQt + SM_QT_F;
    float* sV   = sK + SM_K_F;
    float* sPT  = sV + SM_V_F;
    float* sRed = sPT + SM_PT_F;

    const int tid  = threadIdx.x;
    const int wid  = tid >> 5;
    const int lane = tid & 31;
    const int g    = lane >> 2;
    const int t    = lane & 3;
    const int qw   = 16 * wid;

    const int qb = (gridDim.x - 1) - blockIdx.x;
    const int h  = blockIdx.y;
    const int b  = blockIdx.z;

    const size_t head = ((size_t)(b * NHEADS + h)) * SEQ * HDIM;
    const float* Qb = Q + head + (size_t)qb * 128 * HDIM;
    const float* Kb = K + head;
    const float* Vb = V + head;

    for (int i = tid; i < 128 * 32; i += 256) {
        int c4 = i >> 7;
        int q  = i & 127;
        float4 v = *(const float4*)(Qb + (size_t)q * HDIM + c4 * 4);
        sQt[(4 * c4 + 0) * Q_ST + q] = v.x;
        sQt[(4 * c4 + 1) * Q_ST + q] = v.y;
        sQt[(4 * c4 + 2) * Q_ST + q] = v.z;
        sQt[(4 * c4 + 3) * Q_ST + q] = v.w;
    }

    const int ntiles = 2 * (qb + 1);

    load_k_tile(sK, Kb, tid);            cp_commit();
    load_v_tile(sV, Vb, tid);            cp_commit();

    float m_i[2][2], l_i[2][2];
    float acc_o[16][4];
#pragma unroll
    for (int nf = 0; nf < 2; nf++)
#pragma unroll
        for (int par = 0; par < 2; par++) { m_i[nf][par] = -1e30f; l_i[nf][par] = 0.f; }
#pragma unroll
    for (int i = 0; i < 16; i++)
#pragma unroll
        for (int r = 0; r < 4; r++) acc_o[i][r] = 0.f;

    __syncthreads();

    for (int kb = 0; kb < ntiles; kb++) {
        const bool has_next = (kb + 1) < ntiles;
        if (has_next) {
            load_k_tile(sK + ((kb + 1) & 1) * 64 * K_ST,
                        Kb + (size_t)(kb + 1) * 64 * HDIM, tid);
            cp_commit();
        }
        if (has_next) cp_wait<2>(); else cp_wait<1>();
        __syncthreads();

        const float* cK = sK + (kb & 1) * 64 * K_ST;
        const bool active = (kb * 64) <= (qb * 128 + qw + 15);

        float p[4][2][4];
        if (active) {
#pragma unroll
            for (int mf = 0; mf < 4; mf++)
#pragma unroll
                for (int nf = 0; nf < 2; nf++)
#pragma unroll
                    for (int r = 0; r < 4; r++) p[mf][nf][r] = 0.f;

#pragma unroll 4
            for (int kk = 0; kk < HDIM; kk += 8) {
                uint32_t afr[4][4];
#pragma unroll
                for (int mf = 0; mf < 4; mf++) {
                    const int m = 16 * mf + g;
                    afr[mf][0] = __float_as_uint(cK[(m)     * K_ST + kk + t]);
                    afr[mf][1] = __float_as_uint(cK[(m + 8) * K_ST + kk + t]);
                    afr[mf][2] = __float_as_uint(cK[(m)     * K_ST + kk + t + 4]);
                    afr[mf][3] = __float_as_uint(cK[(m + 8) * K_ST + kk + t + 4]);
                }
                uint32_t bfr[2][2];
#pragma unroll
                for (int nf = 0; nf < 2; nf++) {
                    const int qn = qw + 8 * nf + g;
                    bfr[nf][0] = __float_as_uint(sQt[(kk + t)     * Q_ST + qn]);
                    bfr[nf][1] = __float_as_uint(sQt[(kk + t + 4) * Q_ST + qn]);
                }
#pragma unroll
                for (int mf = 0; mf < 4; mf++)
#pragma unroll
                    for (int nf = 0; nf < 2; nf++)
                        mma_tf32(p[mf][nf], afr[mf], bfr[nf]);
            }

            const bool diag = (kb >= ntiles - 2);
            float mx[2][2] = {{-1e30f, -1e30f}, {-1e30f, -1e30f}};
#pragma unroll
            for (int mf = 0; mf < 4; mf++)
#pragma unroll
                for (int nf = 0; nf < 2; nf++) {
                    const int kg = kb * 64 + 16 * mf + g;
                    const int qc = qb * 128 + qw + 8 * nf + 2 * t;
#pragma unroll
                    for (int e = 0; e < 4; e++) {
                        const int kge = kg + ((e >= 2) ? 8 : 0);
                        const int qce = qc + (e & 1);
                        float v = p[mf][nf][e] * SL2;
                        if (diag && kge > qce) v = -1e30f;
                        p[mf][nf][e] = v;
                    }
                    mx[nf][0] = fmaxf(mx[nf][0], fmaxf(p[mf][nf][0], p[mf][nf][2]));
                    mx[nf][1] = fmaxf(mx[nf][1], fmaxf(p[mf][nf][1], p[mf][nf][3]));
                }
#pragma unroll
            for (int nf = 0; nf < 2; nf++)
#pragma unroll
                for (int par = 0; par < 2; par++) {
                    float v = mx[nf][par];
                    v = fmaxf(v, __shfl_xor_sync(0xffffffffu, v, 4));
                    v = fmaxf(v, __shfl_xor_sync(0xffffffffu, v, 8));
                    v = fmaxf(v, __shfl_xor_sync(0xffffffffu, v, 16));
                    mx[nf][par] = v;
                }
            float alpha[2][2];
#pragma unroll
            for (int nf = 0; nf < 2; nf++)
#pragma unroll
                for (int par = 0; par < 2; par++) {
                    const float m_new = fmaxf(m_i[nf][par], mx[nf][par]);
                    alpha[nf][par] = ex2(m_i[nf][par] - m_new);
                    m_i[nf][par] = m_new;
                }
            float sum[2][2] = {{0.f, 0.f}, {0.f, 0.f}};
#pragma unroll
            for (int mf = 0; mf < 4; mf++)
#pragma unroll
                for (int nf = 0; nf < 2; nf++) {
                    p[mf][nf][0] = ex2(p[mf][nf][0] - m_i[nf][0]);
                    p[mf][nf][1] = ex2(p[mf][nf][1] - m_i[nf][1]);
                    p[mf][nf][2] = ex2(p[mf][nf][2] - m_i[nf][0]);
                    p[mf][nf][3] = ex2(p[mf][nf][3] - m_i[nf][1]);
                    sum[nf][0] += p[mf][nf][0] + p[mf][nf][2];
                    sum[nf][1] += p[mf][nf][1] + p[mf][nf][3];
                }
#pragma unroll
            for (int nf = 0; nf < 2; nf++)
#pragma unroll
                for (int par = 0; par < 2; par++) {
                    float v = sum[nf][par];
                    v += __shfl_xor_sync(0xffffffffu, v, 4);
                    v += __shfl_xor_sync(0xffffffffu, v, 8);
                    v += __shfl_xor_sync(0xffffffffu, v, 16);
                    l_i[nf][par] = l_i[nf][par] * alpha[nf][par] + v;
                }

#pragma unroll
            for (int mf = 0; mf < 4; mf++)
#pragma unroll
                for (int nf = 0; nf < 2; nf++) {
                    const int kr = 16 * mf + g;
                    const int qc = qw + 8 * nf + 2 * t;
                    sPT[(kr)     * P_ST + qc]     = __uint_as_float(f2tf32(p[mf][nf][0]));
                    sPT[(kr)     * P_ST + qc + 1] = __uint_as_float(f2tf32(p[mf][nf][1]));
                    sPT[(kr + 8) * P_ST + qc]     = __uint_as_float(f2tf32(p[mf][nf][2]));
                    sPT[(kr + 8) * P_ST + qc + 1] = __uint_as_float(f2tf32(p[mf][nf][3]));
                }
            if (lane < 4) {
#pragma unroll
                for (int nf = 0; nf < 2; nf++)
#pragma unroll
                    for (int par = 0; par < 2; par++)
                        sRed[qw + 8 * nf + 2 * lane + par] = alpha[nf][par];
            }
            __syncwarp();
            const float al0 = sRed[qw + g];
            const float al1 = sRed[qw + g + 8];
#pragma unroll
            for (int nf2 = 0; nf2 < 16; nf2++) {
                acc_o[nf2][0] *= al0; acc_o[nf2][1] *= al0;
                acc_o[nf2][2] *= al1; acc_o[nf2][3] *= al1;
            }
        }

        if (has_next) cp_wait<1>(); else cp_wait<0>();
        __syncthreads();

        if (active) {
#pragma unroll 2
            for (int kk = 0; kk < 64; kk += 8) {
                uint32_t va[4];
                va[0] = __float_as_uint(sPT[(kk + t)     * P_ST + qw + g]);
                va[1] = __float_as_uint(sPT[(kk + t)     * P_ST + qw + g + 8]);
                va[2] = __float_as_uint(sPT[(kk + t + 4) * P_ST + qw + g]);
                va[3] = __float_as_uint(sPT[(kk + t + 4) * P_ST + qw + g + 8]);
#pragma unroll
                for (int nf2 = 0; nf2 < 16; nf2++) {
                    uint32_t vb[2];
                    vb[0] = __float_as_uint(sV[(kk + t)     * V_ST + 8 * nf2 + g]);
                    vb[1] = __float_as_uint(sV[(kk + t + 4) * V_ST + 8 * nf2 + g]);
                    mma_tf32(acc_o[nf2], va, vb);
                }
            }
        }

        __syncthreads();
        if (has_next) {
            load_v_tile(sV, Vb + (size_t)(kb + 1) * 64 * HDIM, tid);
            cp_commit();
        }
    }

    if (lane < 4) {
#pragma unroll
        for (int nf = 0; nf < 2; nf++)
#pragma unroll
            for (int par = 0; par < 2; par++)
                sRed[qw + 8 * nf + 2 * lane + par] = l_i[nf][par];
    }
    __syncwarp();
    const float il0 = 1.f / sRed[qw + g];
    const float il1 = 1.f / sRed[qw + g + 8];

    const int q0 = qb * 128 + qw + g;
    const int q1 = q0 + 8;
    const size_t base0 = ((size_t)b * SEQ + q0) * DMODEL + h * HDIM;
    const size_t base1 = ((size_t)b * SEQ + q1) * DMODEL + h * HDIM;
#pragma unroll
    for (int nf2 = 0; nf2 < 16; nf2++) {
        const int d = 8 * nf2 + 2 * t;
        float2 v0, v1;
        v0.x = __uint_as_float(f2tf32(acc_o[nf2][0] * il0));
        v0.y = __uint_as_float(f2tf32(acc_o[nf2][1] * il0));
        v1.x = __uint_as_float(f2tf32(acc_o[nf2][2] * il1));
        v1.y = __uint_as_float(f2tf32(acc_o[nf2][3] * il1));
        *(float2*)&O[base0 + d] = v0;
        *(float2*)&O[base1 + d] = v1;
    }
}

// ---------------------------------------------------------------------------
// Launch
// ---------------------------------------------------------------------------
extern "C" void kernel_launch(void* const* d_in, const int* in_sizes, int n_in,
                              void* d_out, int out_size)
{
    const float* x  = (const float*)d_in[0];
    const float* Wq = (const float*)d_in[1];
    const float* bq = (const float*)d_in[2];
    const float* Wk = (const float*)d_in[3];
    const float* bk = (const float*)d_in[4];
    const float* Wv = (const float*)d_in[5];
    const float* bv = (const float*)d_in[6];
    const float* Wo = (const float*)d_in[7];
    const float* bo = (const float*)d_in[8];
    float* out = (float*)d_out;

    float *q, *k, *v, *attn, *xr, *wq, *wk, *wv, *wo;
    cudaGetSymbolAddress((void**)&q,    g_q);
    cudaGetSymbolAddress((void**)&k,    g_k);
    cudaGetSymbolAddress((void**)&v,    g_v);
    cudaGetSymbolAddress((void**)&attn, g_attn);
    cudaGetSymbolAddress((void**)&xr,   g_x);
    cudaGetSymbolAddress((void**)&wq,   g_wq);
    cudaGetSymbolAddress((void**)&wk,   g_wk);
    cudaGetSymbolAddress((void**)&wv,   g_wv);
    cudaGetSymbolAddress((void**)&wo,   g_wo);

    cudaFuncSetAttribute(attn_mma_kernel,
                         cudaFuncAttributeMaxDynamicSharedMemorySize, SMA_BYTES);
    cudaFuncSetAttribute(gemm_tf32_kernel,
                         cudaFuncAttributeMaxDynamicSharedMemorySize, GEMM_SM_BYTES);
    cudaFuncSetAttribute(gemm_qkv_kernel,
                         cudaFuncAttributeMaxDynamicSharedMemorySize, GEMM_SM_BYTES);

    // single fused pre-round for x + 4 weights
    preround5_kernel<<<PR_TOTAL_F4 / 256, 256>>>(
        (const float4*)x,  (float4*)xr,
        (const float4*)Wq, (float4*)wq,
        (const float4*)Wk, (float4*)wk,
        (const float4*)Wv, (float4*)wv,
        (const float4*)Wo, (float4*)wo);

    // fused QKV projection: one launch, one drain tail
    dim3 qkv_grid(GN / 128, M_TOK / 128, 3);   // (16, 64, 3)
    gemm_qkv_kernel<<<qkv_grid, 256, GEMM_SM_BYTES>>>(
        xr, wq, wk, wv, bq, bk, bv, q, k, v);

    attn_mma_kernel<<<dim3(SEQ / 128, NHEADS, BATCH), 256, SMA_BYTES>>>(q, k, v, attn);

    dim3 gemm_grid(GN / 128, M_TOK / 128);     // (16, 64)
    gemm_tf32_kernel<<<gemm_grid, 256, GEMM_SM_BYTES>>>(attn, wo, bo, out, 0);
}